// round 6
// baseline (speedup 1.0000x reference)
#include <cuda_runtime.h>

#define MARGIN 0.5f

// Scratch accumulators (no device allocation allowed -> __device__ globals).
// Zero at module load; last block re-zeros each call (graph-replay safe).
__device__ float        g_total;
__device__ unsigned int g_count;
__device__ unsigned int g_arrive;

// ---------------------------------------------------------------------------
// Fast path: C=64, P=16, N=48, B even. One warp = one problem PAIR (b0,b1).
//
// Index loads exploit pair contiguity (all coalesced, no predication):
//   nn[0..95]  = neg rows of b0 then b1  -> 3 coalesced LDG.32
//   pp[0..31]  = pos rows of b0 then b1  -> 1 coalesced LDG.32
//   counts     -> int2 broadcasts
// Register layout (per lane):
//   nA : b0 neg slot  lane        (all 32 lanes)
//   nB : lanes 0-15 -> b0 slots 32-47 ; lanes 16-31 -> b1 slots 0-15
//   nC : b1 neg slot  16+lane     (all 32 lanes)
//   pv : lanes 0-15 -> b0 pos ; lanes 16-31 -> b1 pos (invalid -> +1e30)
// Loops: grouped-by-4 independent SHFL broadcasts, self-masked overshoot.
// Warp-uniform term skipping: b0 adds nB only if nc0>32; b1 adds nC only if
// nc1>16 -> expected 1.3 terms/lane/iter instead of fixed 2.
// ---------------------------------------------------------------------------
#define FC 64
#define FP 16
#define FN 48
#define FWARPS 8
#define FTHREADS (FWARPS * 32)

__global__ void __launch_bounds__(FTHREADS)
mpcl_fast_kernel(const float* __restrict__ scores,
                 const int*   __restrict__ pos_indices,
                 const int*   __restrict__ neg_indices,
                 const int*   __restrict__ pos_counts,
                 const int*   __restrict__ neg_counts,
                 float*       __restrict__ out,
                 int nPairs)
{
    __shared__ float    s_tot[FWARPS];
    __shared__ unsigned s_cnt[FWARPS];

    const int warp = threadIdx.x >> 5;
    const int lane = threadIdx.x & 31;
    const int q    = blockIdx.x * FWARPS + warp;

    float acc0 = 0.0f, acc1 = 0.0f, acc2 = 0.0f, acc3 = 0.0f;
    unsigned cnt = 0u;

    if (q < nPairs) {
        const int b0 = q * 2;

        const int2 pcv = *reinterpret_cast<const int2*>(pos_counts + b0);
        const int2 ncv = *reinterpret_cast<const int2*>(neg_counts + b0);
        const int pc0 = pcv.x, pc1 = pcv.y;
        const int nc0 = ncv.x, nc1 = ncv.y;

        const float* row0 = scores + (size_t)b0 * FC;
        const float* row1 = row0 + FC;
        const float* rowB = (lane < 16) ? row0 : row1;
        const int*   nn   = neg_indices + (size_t)b0 * FN;   // 96 contiguous
        const int*   pp   = pos_indices + (size_t)b0 * FP;   // 32 contiguous

        // coalesced index loads (always in-bounds; index values in [0,C))
        const int jA = nn[lane];
        const int jB = nn[lane + 32];
        const int jC = nn[lane + 64];
        const int jP = pp[lane];

        // gathers (independent -> MLP 4)
        const float gA = row0[jA];
        const float gB = rowB[jB];
        const float gC = row1[jC];
        const float gP = rowB[jP];

        // masks
        const int  pcOwn  = (lane < 16) ? pc0 : pc1;
        const float pv    = ((lane & 15) < pcOwn) ? gP : 1e30f;
        const float nA    = (lane < nc0) ? gA : -1e30f;
        const bool  bVal  = (lane < 16) ? (lane + 32 < nc0) : (lane - 16 < nc1);
        const float nBm   = bVal ? gB : -1e30f;
        const float nB0   = (lane < 16) ? nBm : -1e30f;   // b0's view of reg B
        const float nB1   = (lane < 16) ? -1e30f : nBm;   // b1's view of reg B
        const float nC    = (lane + 16 < nc1) ? gC : -1e30f;

        cnt = (unsigned)(pc0 * nc0) + (unsigned)(pc1 * nc1);

        // ---- problem b0: positives broadcast from lanes 0..15 ----
        const int it0 = (nc0 > 0) ? pc0 : 0;
        if (nc0 > 32) {
            for (int pg = 0; pg < it0; pg += 4) {
                const float x0 = __shfl_sync(0xffffffffu, pv, pg + 0);
                const float x1 = __shfl_sync(0xffffffffu, pv, pg + 1);
                const float x2 = __shfl_sync(0xffffffffu, pv, pg + 2);
                const float x3 = __shfl_sync(0xffffffffu, pv, pg + 3);
                const float a0 = MARGIN - x0, a1 = MARGIN - x1;
                const float a2 = MARGIN - x2, a3 = MARGIN - x3;
                acc0 += fmaxf(a0 + nA, 0.0f) + fmaxf(a0 + nB0, 0.0f);
                acc1 += fmaxf(a1 + nA, 0.0f) + fmaxf(a1 + nB0, 0.0f);
                acc2 += fmaxf(a2 + nA, 0.0f) + fmaxf(a2 + nB0, 0.0f);
                acc3 += fmaxf(a3 + nA, 0.0f) + fmaxf(a3 + nB0, 0.0f);
            }
        } else {
            for (int pg = 0; pg < it0; pg += 4) {
                const float x0 = __shfl_sync(0xffffffffu, pv, pg + 0);
                const float x1 = __shfl_sync(0xffffffffu, pv, pg + 1);
                const float x2 = __shfl_sync(0xffffffffu, pv, pg + 2);
                const float x3 = __shfl_sync(0xffffffffu, pv, pg + 3);
                acc0 += fmaxf(MARGIN - x0 + nA, 0.0f);
                acc1 += fmaxf(MARGIN - x1 + nA, 0.0f);
                acc2 += fmaxf(MARGIN - x2 + nA, 0.0f);
                acc3 += fmaxf(MARGIN - x3 + nA, 0.0f);
            }
        }

        // ---- problem b1: positives broadcast from lanes 16..31 ----
        const int it1 = (nc1 > 0) ? pc1 : 0;
        if (nc1 > 16) {
            for (int pg = 0; pg < it1; pg += 4) {
                const float x0 = __shfl_sync(0xffffffffu, pv, 16 + pg + 0);
                const float x1 = __shfl_sync(0xffffffffu, pv, 16 + pg + 1);
                const float x2 = __shfl_sync(0xffffffffu, pv, 16 + pg + 2);
                const float x3 = __shfl_sync(0xffffffffu, pv, 16 + pg + 3);
                const float a0 = MARGIN - x0, a1 = MARGIN - x1;
                const float a2 = MARGIN - x2, a3 = MARGIN - x3;
                acc0 += fmaxf(a0 + nB1, 0.0f) + fmaxf(a0 + nC, 0.0f);
                acc1 += fmaxf(a1 + nB1, 0.0f) + fmaxf(a1 + nC, 0.0f);
                acc2 += fmaxf(a2 + nB1, 0.0f) + fmaxf(a2 + nC, 0.0f);
                acc3 += fmaxf(a3 + nB1, 0.0f) + fmaxf(a3 + nC, 0.0f);
            }
        } else {
            for (int pg = 0; pg < it1; pg += 4) {
                const float x0 = __shfl_sync(0xffffffffu, pv, 16 + pg + 0);
                const float x1 = __shfl_sync(0xffffffffu, pv, 16 + pg + 1);
                const float x2 = __shfl_sync(0xffffffffu, pv, 16 + pg + 2);
                const float x3 = __shfl_sync(0xffffffffu, pv, 16 + pg + 3);
                acc0 += fmaxf(MARGIN - x0 + nB1, 0.0f);
                acc1 += fmaxf(MARGIN - x1 + nB1, 0.0f);
                acc2 += fmaxf(MARGIN - x2 + nB1, 0.0f);
                acc3 += fmaxf(MARGIN - x3 + nB1, 0.0f);
            }
        }
    }

    float accs = (acc0 + acc1) + (acc2 + acc3);
    #pragma unroll
    for (int o = 16; o > 0; o >>= 1)
        accs += __shfl_xor_sync(0xffffffffu, accs, o);

    if (lane == 0) { s_tot[warp] = accs; s_cnt[warp] = cnt; }
    __syncthreads();

    if (threadIdx.x == 0) {
        float    t = 0.0f;
        unsigned c = 0u;
        #pragma unroll
        for (int i = 0; i < FWARPS; i++) { t += s_tot[i]; c += s_cnt[i]; }
        asm volatile("red.add.release.gpu.f32 [%0], %1;"
                     :: "l"(&g_total), "f"(t) : "memory");
        asm volatile("red.add.release.gpu.u32 [%0], %1;"
                     :: "l"(&g_count), "r"(c) : "memory");
        unsigned ticket;
        asm volatile("atom.add.acq_rel.gpu.u32 %0, [%1], %2;"
                     : "=r"(ticket) : "l"(&g_arrive), "r"(1u) : "memory");
        if (ticket == (unsigned)gridDim.x - 1u) {
            float tv; unsigned cv;
            asm volatile("ld.acquire.gpu.f32 %0, [%1];"
                         : "=f"(tv) : "l"(&g_total) : "memory");
            asm volatile("ld.acquire.gpu.u32 %0, [%1];"
                         : "=r"(cv) : "l"(&g_count) : "memory");
            out[0] = (cv > 0u) ? (tv / (float)cv) : 0.0f;
            g_total = 0.0f; g_count = 0u; g_arrive = 0u;
        }
    }
}

// ---------------------------------------------------------------------------
// Generic fallback (round-5 proven kernel), used only if shape differs.
// ---------------------------------------------------------------------------
#define GWARPS 16
#define GTHREADS (GWARPS * 32)

__global__ void __launch_bounds__(GTHREADS, 4)
mpcl_generic_kernel(const float* __restrict__ scores,
                    const int*   __restrict__ pos_indices,
                    const int*   __restrict__ neg_indices,
                    const int*   __restrict__ pos_counts,
                    const int*   __restrict__ neg_counts,
                    float*       __restrict__ out,
                    int B, int C, int P, int N, int nPairs)
{
    __shared__ float    s_tot[GWARPS];
    __shared__ unsigned s_cnt[GWARPS];

    const int warp    = threadIdx.x >> 5;
    const int lane    = threadIdx.x & 31;
    const int gwarp   = blockIdx.x * GWARPS + warp;
    const int wstride = gridDim.x * GWARPS;
    const bool loHalf = (lane < 16);

    float    acc0 = 0.0f, acc1 = 0.0f;
    unsigned cnt  = 0u;

    for (int q = gwarp; q < nPairs; q += wstride) {
        const int  b0   = q * 2;
        const int  b1   = b0 + 1;
        const bool has1 = (b1 < B);

        const int pc0 = min(pos_counts[b0], 16);
        const int nc0 = neg_counts[b0];
        const int pc1 = has1 ? min(pos_counts[b1], 16) : 0;
        const int nc1 = has1 ? neg_counts[b1]          : 0;

        const float* s0  = scores + (size_t)b0 * (size_t)C;
        const float* s1  = scores + (size_t)b1 * (size_t)C;
        const int*   n0p = neg_indices + (size_t)b0 * (size_t)N;
        const int*   n1p = neg_indices + (size_t)b1 * (size_t)N;

        const int    slot  = lane & 15;
        const bool   myOk  = loHalf || has1;
        const int*   pbase = loHalf ? (pos_indices + (size_t)b0 * (size_t)P)
                                    : (pos_indices + (size_t)b1 * (size_t)P);
        const int    jp    = (myOk && slot < P) ? pbase[slot] : 0;
        const float* sbase = loHalf ? s0 : s1;
        float pv = myOk ? sbase[jp] : 1e30f;
        const int pcOwn = loHalf ? pc0 : pc1;
        pv = (slot < pcOwn) ? pv : 1e30f;

        const int j00 = (lane      < N) ? n0p[lane]      : 0;
        const int j01 = (lane + 32 < N) ? n0p[lane + 32] : 0;
        float n00 = (lane      < nc0) ? s0[j00] : -1e30f;
        float n01 = (lane + 32 < nc0) ? s0[j01] : -1e30f;

        float n10 = -1e30f, n11 = -1e30f;
        if (has1) {
            const int j10 = (lane      < N) ? n1p[lane]      : 0;
            const int j11 = (lane + 32 < N) ? n1p[lane + 32] : 0;
            n10 = (lane      < nc1) ? s1[j10] : -1e30f;
            n11 = (lane + 32 < nc1) ? s1[j11] : -1e30f;
        }

        cnt += (unsigned)(pc0 * nc0) + (unsigned)(pc1 * nc1);

        const int it0 = (nc0 > 0) ? pc0 : 0;
        for (int pg = 0; pg < it0; pg += 4) {
            const float x0 = __shfl_sync(0xffffffffu, pv, pg + 0);
            const float x1 = __shfl_sync(0xffffffffu, pv, pg + 1);
            const float x2 = __shfl_sync(0xffffffffu, pv, pg + 2);
            const float x3 = __shfl_sync(0xffffffffu, pv, pg + 3);
            const float a0 = MARGIN - x0, a1 = MARGIN - x1;
            const float a2 = MARGIN - x2, a3 = MARGIN - x3;
            acc0 += fmaxf(a0 + n00, 0.0f) + fmaxf(a1 + n00, 0.0f)
                  + fmaxf(a2 + n00, 0.0f) + fmaxf(a3 + n00, 0.0f);
            acc1 += fmaxf(a0 + n01, 0.0f) + fmaxf(a1 + n01, 0.0f)
                  + fmaxf(a2 + n01, 0.0f) + fmaxf(a3 + n01, 0.0f);
        }
        const int it1 = (nc1 > 0) ? pc1 : 0;
        for (int pg = 0; pg < it1; pg += 4) {
            const float x0 = __shfl_sync(0xffffffffu, pv, 16 + pg + 0);
            const float x1 = __shfl_sync(0xffffffffu, pv, 16 + pg + 1);
            const float x2 = __shfl_sync(0xffffffffu, pv, 16 + pg + 2);
            const float x3 = __shfl_sync(0xffffffffu, pv, 16 + pg + 3);
            const float a0 = MARGIN - x0, a1 = MARGIN - x1;
            const float a2 = MARGIN - x2, a3 = MARGIN - x3;
            acc0 += fmaxf(a0 + n10, 0.0f) + fmaxf(a1 + n10, 0.0f)
                  + fmaxf(a2 + n10, 0.0f) + fmaxf(a3 + n10, 0.0f);
            acc1 += fmaxf(a0 + n11, 0.0f) + fmaxf(a1 + n11, 0.0f)
                  + fmaxf(a2 + n11, 0.0f) + fmaxf(a3 + n11, 0.0f);
        }
    }

    float accs = acc0 + acc1;
    #pragma unroll
    for (int o = 16; o > 0; o >>= 1)
        accs += __shfl_xor_sync(0xffffffffu, accs, o);

    if (lane == 0) { s_tot[warp] = accs; s_cnt[warp] = cnt; }
    __syncthreads();

    if (threadIdx.x == 0) {
        float    t = 0.0f;
        unsigned c = 0u;
        #pragma unroll
        for (int i = 0; i < GWARPS; i++) { t += s_tot[i]; c += s_cnt[i]; }
        asm volatile("red.add.release.gpu.f32 [%0], %1;"
                     :: "l"(&g_total), "f"(t) : "memory");
        asm volatile("red.add.release.gpu.u32 [%0], %1;"
                     :: "l"(&g_count), "r"(c) : "memory");
        unsigned ticket;
        asm volatile("atom.add.acq_rel.gpu.u32 %0, [%1], %2;"
                     : "=r"(ticket) : "l"(&g_arrive), "r"(1u) : "memory");
        if (ticket == (unsigned)gridDim.x - 1u) {
            float tv; unsigned cv;
            asm volatile("ld.acquire.gpu.f32 %0, [%1];"
                         : "=f"(tv) : "l"(&g_total) : "memory");
            asm volatile("ld.acquire.gpu.u32 %0, [%1];"
                         : "=r"(cv) : "l"(&g_count) : "memory");
            out[0] = (cv > 0u) ? (tv / (float)cv) : 0.0f;
            g_total = 0.0f; g_count = 0u; g_arrive = 0u;
        }
    }
}

extern "C" void kernel_launch(void* const* d_in, const int* in_sizes, int n_in,
                              void* d_out, int out_size)
{
    const float* scores      = (const float*)d_in[0];
    const int*   pos_indices = (const int*)  d_in[1];
    const int*   neg_indices = (const int*)  d_in[2];
    const int*   pos_counts  = (const int*)  d_in[3];
    const int*   neg_counts  = (const int*)  d_in[4];
    float*       out         = (float*)d_out;

    const int B = in_sizes[3];
    const int C = in_sizes[0] / B;
    const int P = in_sizes[1] / B;
    const int N = in_sizes[2] / B;

    if (C == FC && P == FP && N == FN && (B % 2) == 0) {
        const int nPairs = B / 2;
        const int blocks = (nPairs + FWARPS - 1) / FWARPS;
        mpcl_fast_kernel<<<blocks, FTHREADS>>>(
            scores, pos_indices, neg_indices, pos_counts, neg_counts, out,
            nPairs);
    } else {
        const int nPairs = (B + 1) / 2;
        int blocks = (nPairs + GWARPS * 2 - 1) / (GWARPS * 2);
        if (blocks > 592) blocks = 592;
        if (blocks < 1)   blocks = 1;
        mpcl_generic_kernel<<<blocks, GTHREADS>>>(
            scores, pos_indices, neg_indices, pos_counts, neg_counts, out,
            B, C, P, N, nPairs);
    }
}

// round 7
// speedup vs baseline: 1.1830x; 1.1830x over previous
#include <cuda_runtime.h>

#define MARGIN 0.5f

// Scratch accumulators (no device allocation allowed -> __device__ globals).
// Zero at module load; last block re-zeros each call (graph-replay safe).
__device__ float        g_total;
__device__ unsigned int g_count;
__device__ unsigned int g_arrive;

// ---------------------------------------------------------------------------
// Fast path: C=64, P=16, N=48, B%4==0. One warp = one QUAD of problems
// (two adjacent pairs). ALL 18 loads hoisted & independent before compute:
//   2x int4 count broadcasts, 6 coalesced neg-index LDGs, 2 pos-index LDGs,
//   then 8 gathers issued back-to-back -> the two DRAM round-trips
//   (indices, gathers) are each paid ONCE per 4 problems.
// Per-pair register layout (as round 6):
//   nA: prob-even neg slots 0-31; nB: lanes 0-15 = prob-even slots 32-47,
//   lanes 16-31 = prob-odd slots 0-15; nC: prob-odd slots 16-47;
//   pv: lanes 0-15 = prob-even positives, 16-31 = prob-odd (invalid -> +1e30).
// Loops: grouped-by-4 independent SHFL broadcasts, fully self-masking
// (+1e30 pos / -1e30 neg make relu terms exactly 0). No branch variants.
// ---------------------------------------------------------------------------
#define FWARPS 8
#define FTHREADS (FWARPS * 32)

__global__ void __launch_bounds__(FTHREADS)
mpcl_fast_kernel(const float* __restrict__ scores,
                 const int*   __restrict__ pos_indices,
                 const int*   __restrict__ neg_indices,
                 const int*   __restrict__ pos_counts,
                 const int*   __restrict__ neg_counts,
                 float*       __restrict__ out,
                 int nQuads)
{
    __shared__ float    s_tot[FWARPS];
    __shared__ unsigned s_cnt[FWARPS];

    const int warp = threadIdx.x >> 5;
    const int lane = threadIdx.x & 31;
    const int q    = blockIdx.x * FWARPS + warp;

    float acc0 = 0.0f, acc1 = 0.0f, acc2 = 0.0f, acc3 = 0.0f;
    unsigned cnt = 0u;

    if (q < nQuads) {
        const int b0 = q * 4;

        // ---- hoisted loads: counts, indices (all independent) ----
        const int4 pcv = *reinterpret_cast<const int4*>(pos_counts + b0);
        const int4 ncv = *reinterpret_cast<const int4*>(neg_counts + b0);

        const int* nnA = neg_indices + (size_t)b0 * 48;   // pair A: 96 ints
        const int* nnB = nnA + 96;                        // pair B: 96 ints
        const int* ppA = pos_indices + (size_t)b0 * 16;   // pair A: 32 ints
        const int* ppB = ppA + 32;                        // pair B: 32 ints

        const int jA0 = nnA[lane];
        const int jA1 = nnA[lane + 32];
        const int jA2 = nnA[lane + 64];
        const int jPA = ppA[lane];
        const int jB0 = nnB[lane];
        const int jB1 = nnB[lane + 32];
        const int jB2 = nnB[lane + 64];
        const int jPB = ppB[lane];

        // ---- hoisted gathers: 8 back-to-back (one amortized latency) ----
        const float* r0 = scores + (size_t)b0 * 64;
        const float* r1 = r0 + 64;
        const float* r2 = r0 + 128;
        const float* r3 = r0 + 192;
        const float* rA = (lane < 16) ? r0 : r1;   // mixed row, pair A
        const float* rB = (lane < 16) ? r2 : r3;   // mixed row, pair B

        const float gA0 = r0[jA0];
        const float gA1 = rA[jA1];
        const float gA2 = r1[jA2];
        const float gPA = rA[jPA];
        const float gB0 = r2[jB0];
        const float gB1 = rB[jB1];
        const float gB2 = r3[jB2];
        const float gPB = rB[jPB];

        const bool lo16  = (lane < 16);
        const int  slot  = lane & 15;

        // ---- pair A masks (problems b0, b0+1) ----
        const int pc0 = pcv.x, pc1 = pcv.y;
        const int nc0 = ncv.x, nc1 = ncv.y;
        const float nA_A  = (lane < nc0) ? gA0 : -1e30f;
        const bool  bvA   = lo16 ? (lane + 32 < nc0) : (lane - 16 < nc1);
        const float nBmA  = bvA ? gA1 : -1e30f;
        const float nB0_A = lo16 ? nBmA : -1e30f;
        const float nB1_A = lo16 ? -1e30f : nBmA;
        const float nC_A  = (lane + 16 < nc1) ? gA2 : -1e30f;
        const int   pcOwnA = lo16 ? pc0 : pc1;
        const float pvA    = (slot < pcOwnA) ? gPA : 1e30f;

        // ---- pair B masks (problems b0+2, b0+3) ----
        const int pc2 = pcv.z, pc3 = pcv.w;
        const int nc2 = ncv.z, nc3 = ncv.w;
        const float nA_B  = (lane < nc2) ? gB0 : -1e30f;
        const bool  bvB   = lo16 ? (lane + 32 < nc2) : (lane - 16 < nc3);
        const float nBmB  = bvB ? gB1 : -1e30f;
        const float nB0_B = lo16 ? nBmB : -1e30f;
        const float nB1_B = lo16 ? -1e30f : nBmB;
        const float nC_B  = (lane + 16 < nc3) ? gB2 : -1e30f;
        const int   pcOwnB = lo16 ? pc2 : pc3;
        const float pvB    = (slot < pcOwnB) ? gPB : 1e30f;

        cnt = (unsigned)(pc0 * nc0) + (unsigned)(pc1 * nc1)
            + (unsigned)(pc2 * nc2) + (unsigned)(pc3 * nc3);

        // ---- problem b0 ----
        const int it0 = (nc0 > 0) ? pc0 : 0;
        for (int pg = 0; pg < it0; pg += 4) {
            const float a0 = MARGIN - __shfl_sync(0xffffffffu, pvA, pg + 0);
            const float a1 = MARGIN - __shfl_sync(0xffffffffu, pvA, pg + 1);
            const float a2 = MARGIN - __shfl_sync(0xffffffffu, pvA, pg + 2);
            const float a3 = MARGIN - __shfl_sync(0xffffffffu, pvA, pg + 3);
            acc0 += fmaxf(a0 + nA_A, 0.0f) + fmaxf(a0 + nB0_A, 0.0f);
            acc1 += fmaxf(a1 + nA_A, 0.0f) + fmaxf(a1 + nB0_A, 0.0f);
            acc2 += fmaxf(a2 + nA_A, 0.0f) + fmaxf(a2 + nB0_A, 0.0f);
            acc3 += fmaxf(a3 + nA_A, 0.0f) + fmaxf(a3 + nB0_A, 0.0f);
        }
        // ---- problem b0+1 ----
        const int it1 = (nc1 > 0) ? pc1 : 0;
        for (int pg = 0; pg < it1; pg += 4) {
            const float a0 = MARGIN - __shfl_sync(0xffffffffu, pvA, 16 + pg + 0);
            const float a1 = MARGIN - __shfl_sync(0xffffffffu, pvA, 16 + pg + 1);
            const float a2 = MARGIN - __shfl_sync(0xffffffffu, pvA, 16 + pg + 2);
            const float a3 = MARGIN - __shfl_sync(0xffffffffu, pvA, 16 + pg + 3);
            acc0 += fmaxf(a0 + nB1_A, 0.0f) + fmaxf(a0 + nC_A, 0.0f);
            acc1 += fmaxf(a1 + nB1_A, 0.0f) + fmaxf(a1 + nC_A, 0.0f);
            acc2 += fmaxf(a2 + nB1_A, 0.0f) + fmaxf(a2 + nC_A, 0.0f);
            acc3 += fmaxf(a3 + nB1_A, 0.0f) + fmaxf(a3 + nC_A, 0.0f);
        }
        // ---- problem b0+2 ----
        const int it2 = (nc2 > 0) ? pc2 : 0;
        for (int pg = 0; pg < it2; pg += 4) {
            const float a0 = MARGIN - __shfl_sync(0xffffffffu, pvB, pg + 0);
            const float a1 = MARGIN - __shfl_sync(0xffffffffu, pvB, pg + 1);
            const float a2 = MARGIN - __shfl_sync(0xffffffffu, pvB, pg + 2);
            const float a3 = MARGIN - __shfl_sync(0xffffffffu, pvB, pg + 3);
            acc0 += fmaxf(a0 + nA_B, 0.0f) + fmaxf(a0 + nB0_B, 0.0f);
            acc1 += fmaxf(a1 + nA_B, 0.0f) + fmaxf(a1 + nB0_B, 0.0f);
            acc2 += fmaxf(a2 + nA_B, 0.0f) + fmaxf(a2 + nB0_B, 0.0f);
            acc3 += fmaxf(a3 + nA_B, 0.0f) + fmaxf(a3 + nB0_B, 0.0f);
        }
        // ---- problem b0+3 ----
        const int it3 = (nc3 > 0) ? pc3 : 0;
        for (int pg = 0; pg < it3; pg += 4) {
            const float a0 = MARGIN - __shfl_sync(0xffffffffu, pvB, 16 + pg + 0);
            const float a1 = MARGIN - __shfl_sync(0xffffffffu, pvB, 16 + pg + 1);
            const float a2 = MARGIN - __shfl_sync(0xffffffffu, pvB, 16 + pg + 2);
            const float a3 = MARGIN - __shfl_sync(0xffffffffu, pvB, 16 + pg + 3);
            acc0 += fmaxf(a0 + nB1_B, 0.0f) + fmaxf(a0 + nC_B, 0.0f);
            acc1 += fmaxf(a1 + nB1_B, 0.0f) + fmaxf(a1 + nC_B, 0.0f);
            acc2 += fmaxf(a2 + nB1_B, 0.0f) + fmaxf(a2 + nC_B, 0.0f);
            acc3 += fmaxf(a3 + nB1_B, 0.0f) + fmaxf(a3 + nC_B, 0.0f);
        }
    }

    float accs = (acc0 + acc1) + (acc2 + acc3);
    #pragma unroll
    for (int o = 16; o > 0; o >>= 1)
        accs += __shfl_xor_sync(0xffffffffu, accs, o);

    if (lane == 0) { s_tot[warp] = accs; s_cnt[warp] = cnt; }
    __syncthreads();

    if (threadIdx.x == 0) {
        float    t = 0.0f;
        unsigned c = 0u;
        #pragma unroll
        for (int i = 0; i < FWARPS; i++) { t += s_tot[i]; c += s_cnt[i]; }
        // Fence-free finalize (no CCTL.IVALL): release REDs + acq_rel ticket.
        asm volatile("red.add.release.gpu.f32 [%0], %1;"
                     :: "l"(&g_total), "f"(t) : "memory");
        asm volatile("red.add.release.gpu.u32 [%0], %1;"
                     :: "l"(&g_count), "r"(c) : "memory");
        unsigned ticket;
        asm volatile("atom.add.acq_rel.gpu.u32 %0, [%1], %2;"
                     : "=r"(ticket) : "l"(&g_arrive), "r"(1u) : "memory");
        if (ticket == (unsigned)gridDim.x - 1u) {
            float tv; unsigned cv;
            asm volatile("ld.acquire.gpu.f32 %0, [%1];"
                         : "=f"(tv) : "l"(&g_total) : "memory");
            asm volatile("ld.acquire.gpu.u32 %0, [%1];"
                         : "=r"(cv) : "l"(&g_count) : "memory");
            out[0] = (cv > 0u) ? (tv / (float)cv) : 0.0f;
            g_total = 0.0f; g_count = 0u; g_arrive = 0u;
        }
    }
}

// ---------------------------------------------------------------------------
// Generic fallback (round-5 proven kernel), used only if shape differs.
// ---------------------------------------------------------------------------
#define GWARPS 16
#define GTHREADS (GWARPS * 32)

__global__ void __launch_bounds__(GTHREADS, 4)
mpcl_generic_kernel(const float* __restrict__ scores,
                    const int*   __restrict__ pos_indices,
                    const int*   __restrict__ neg_indices,
                    const int*   __restrict__ pos_counts,
                    const int*   __restrict__ neg_counts,
                    float*       __restrict__ out,
                    int B, int C, int P, int N, int nPairs)
{
    __shared__ float    s_tot[GWARPS];
    __shared__ unsigned s_cnt[GWARPS];

    const int warp    = threadIdx.x >> 5;
    const int lane    = threadIdx.x & 31;
    const int gwarp   = blockIdx.x * GWARPS + warp;
    const int wstride = gridDim.x * GWARPS;
    const bool loHalf = (lane < 16);

    float    acc0 = 0.0f, acc1 = 0.0f;
    unsigned cnt  = 0u;

    for (int q = gwarp; q < nPairs; q += wstride) {
        const int  b0   = q * 2;
        const int  b1   = b0 + 1;
        const bool has1 = (b1 < B);

        const int pc0 = min(pos_counts[b0], 16);
        const int nc0 = neg_counts[b0];
        const int pc1 = has1 ? min(pos_counts[b1], 16) : 0;
        const int nc1 = has1 ? neg_counts[b1]          : 0;

        const float* s0  = scores + (size_t)b0 * (size_t)C;
        const float* s1  = scores + (size_t)b1 * (size_t)C;
        const int*   n0p = neg_indices + (size_t)b0 * (size_t)N;
        const int*   n1p = neg_indices + (size_t)b1 * (size_t)N;

        const int    slot  = lane & 15;
        const bool   myOk  = loHalf || has1;
        const int*   pbase = loHalf ? (pos_indices + (size_t)b0 * (size_t)P)
                                    : (pos_indices + (size_t)b1 * (size_t)P);
        const int    jp    = (myOk && slot < P) ? pbase[slot] : 0;
        const float* sbase = loHalf ? s0 : s1;
        float pv = myOk ? sbase[jp] : 1e30f;
        const int pcOwn = loHalf ? pc0 : pc1;
        pv = (slot < pcOwn) ? pv : 1e30f;

        const int j00 = (lane      < N) ? n0p[lane]      : 0;
        const int j01 = (lane + 32 < N) ? n0p[lane + 32] : 0;
        float n00 = (lane      < nc0) ? s0[j00] : -1e30f;
        float n01 = (lane + 32 < nc0) ? s0[j01] : -1e30f;

        float n10 = -1e30f, n11 = -1e30f;
        if (has1) {
            const int j10 = (lane      < N) ? n1p[lane]      : 0;
            const int j11 = (lane + 32 < N) ? n1p[lane + 32] : 0;
            n10 = (lane      < nc1) ? s1[j10] : -1e30f;
            n11 = (lane + 32 < nc1) ? s1[j11] : -1e30f;
        }

        cnt += (unsigned)(pc0 * nc0) + (unsigned)(pc1 * nc1);

        const int it0 = (nc0 > 0) ? pc0 : 0;
        for (int pg = 0; pg < it0; pg += 4) {
            const float x0 = __shfl_sync(0xffffffffu, pv, pg + 0);
            const float x1 = __shfl_sync(0xffffffffu, pv, pg + 1);
            const float x2 = __shfl_sync(0xffffffffu, pv, pg + 2);
            const float x3 = __shfl_sync(0xffffffffu, pv, pg + 3);
            const float a0 = MARGIN - x0, a1 = MARGIN - x1;
            const float a2 = MARGIN - x2, a3 = MARGIN - x3;
            acc0 += fmaxf(a0 + n00, 0.0f) + fmaxf(a1 + n00, 0.0f)
                  + fmaxf(a2 + n00, 0.0f) + fmaxf(a3 + n00, 0.0f);
            acc1 += fmaxf(a0 + n01, 0.0f) + fmaxf(a1 + n01, 0.0f)
                  + fmaxf(a2 + n01, 0.0f) + fmaxf(a3 + n01, 0.0f);
        }
        const int it1 = (nc1 > 0) ? pc1 : 0;
        for (int pg = 0; pg < it1; pg += 4) {
            const float x0 = __shfl_sync(0xffffffffu, pv, 16 + pg + 0);
            const float x1 = __shfl_sync(0xffffffffu, pv, 16 + pg + 1);
            const float x2 = __shfl_sync(0xffffffffu, pv, 16 + pg + 2);
            const float x3 = __shfl_sync(0xffffffffu, pv, 16 + pg + 3);
            const float a0 = MARGIN - x0, a1 = MARGIN - x1;
            const float a2 = MARGIN - x2, a3 = MARGIN - x3;
            acc0 += fmaxf(a0 + n10, 0.0f) + fmaxf(a1 + n10, 0.0f)
                  + fmaxf(a2 + n10, 0.0f) + fmaxf(a3 + n10, 0.0f);
            acc1 += fmaxf(a0 + n11, 0.0f) + fmaxf(a1 + n11, 0.0f)
                  + fmaxf(a2 + n11, 0.0f) + fmaxf(a3 + n11, 0.0f);
        }
    }

    float accs = acc0 + acc1;
    #pragma unroll
    for (int o = 16; o > 0; o >>= 1)
        accs += __shfl_xor_sync(0xffffffffu, accs, o);

    if (lane == 0) { s_tot[warp] = accs; s_cnt[warp] = cnt; }
    __syncthreads();

    if (threadIdx.x == 0) {
        float    t = 0.0f;
        unsigned c = 0u;
        #pragma unroll
        for (int i = 0; i < GWARPS; i++) { t += s_tot[i]; c += s_cnt[i]; }
        asm volatile("red.add.release.gpu.f32 [%0], %1;"
                     :: "l"(&g_total), "f"(t) : "memory");
        asm volatile("red.add.release.gpu.u32 [%0], %1;"
                     :: "l"(&g_count), "r"(c) : "memory");
        unsigned ticket;
        asm volatile("atom.add.acq_rel.gpu.u32 %0, [%1], %2;"
                     : "=r"(ticket) : "l"(&g_arrive), "r"(1u) : "memory");
        if (ticket == (unsigned)gridDim.x - 1u) {
            float tv; unsigned cv;
            asm volatile("ld.acquire.gpu.f32 %0, [%1];"
                         : "=f"(tv) : "l"(&g_total) : "memory");
            asm volatile("ld.acquire.gpu.u32 %0, [%1];"
                         : "=r"(cv) : "l"(&g_count) : "memory");
            out[0] = (cv > 0u) ? (tv / (float)cv) : 0.0f;
            g_total = 0.0f; g_count = 0u; g_arrive = 0u;
        }
    }
}

extern "C" void kernel_launch(void* const* d_in, const int* in_sizes, int n_in,
                              void* d_out, int out_size)
{
    const float* scores      = (const float*)d_in[0];
    const int*   pos_indices = (const int*)  d_in[1];
    const int*   neg_indices = (const int*)  d_in[2];
    const int*   pos_counts  = (const int*)  d_in[3];
    const int*   neg_counts  = (const int*)  d_in[4];
    float*       out         = (float*)d_out;

    const int B = in_sizes[3];
    const int C = in_sizes[0] / B;
    const int P = in_sizes[1] / B;
    const int N = in_sizes[2] / B;

    if (C == 64 && P == 16 && N == 48 && (B % 4) == 0) {
        const int nQuads = B / 4;
        const int blocks = (nQuads + FWARPS - 1) / FWARPS;
        mpcl_fast_kernel<<<blocks, FTHREADS>>>(
            scores, pos_indices, neg_indices, pos_counts, neg_counts, out,
            nQuads);
    } else {
        const int nPairs = (B + 1) / 2;
        int blocks = (nPairs + GWARPS * 2 - 1) / (GWARPS * 2);
        if (blocks > 592) blocks = 592;
        if (blocks < 1)   blocks = 1;
        mpcl_generic_kernel<<<blocks, GTHREADS>>>(
            scores, pos_indices, neg_indices, pos_counts, neg_counts, out,
            B, C, P, N, nPairs);
    }
}